// round 8
// baseline (speedup 1.0000x reference)
#include <cuda_runtime.h>
#include <math.h>

#define SS 4096
#define BB 64
#define HH 512
#define NCH 64          // s-chunks of 64 rows
#define NITEM (BB * NCH)  // 4096 work items
#define GRID2 296       // persistent k2 grid: 2 CTAs/SM * 148
#define KS 32           // split-K slices for final GEMM
#define KSL 32          // K per slice (2H / KS)
#define CEXP 32.0f      // fixed softmax shift (cancels exactly in acc/l)

// Scratch (device globals — no allocation allowed)
__device__ float g_u[BB * HH];               // u[b,j] = sum_i W_a[i,j] h_t[b,i]
__device__ float g_ct[BB * HH];              // c_t
__device__ float g_pl[BB * NCH];             // partial sum-exp per (b,chunk)
__device__ float g_pacc[BB * NCH * HH];      // partial weighted accumulators (8 MB)
__device__ float g_opart[KS * HH * BB];      // [ks][o][b] GEMM partials (4 MB)

// ---------------------------------------------------------------------------
// K1: u[b,j] = sum_i W_a[i,j] * h_t[b,i].  W_a read EXACTLY ONCE total.
// ---------------------------------------------------------------------------
__global__ void __launch_bounds__(512) k1_proj(const float* __restrict__ W_a,
                                               const float* __restrict__ h_t) {
    __shared__ float h_sh[64][65];
    __shared__ float W_sh[64][16];
    __shared__ float u_sh[16][65];
    const int t = threadIdx.x;
    const int jl = t >> 5, lane = t & 31;
    const int j0 = blockIdx.x * 16;

    float acc0 = 0.f, acc1 = 0.f;
    for (int c = 0; c < 8; c++) {
        const int ibase = c * 64;
        for (int idx = t; idx < 64 * 64; idx += 512) {
            const int bb = idx >> 6, il = idx & 63;
            h_sh[il][bb] = h_t[bb * HH + ibase + il];
        }
        for (int idx = t; idx < 64 * 16; idx += 512) {
            const int il = idx >> 4, jj = idx & 15;
            W_sh[il][jj] = W_a[(ibase + il) * HH + j0 + jj];
        }
        __syncthreads();
#pragma unroll 16
        for (int il = 0; il < 64; il++) {
            const float wv = W_sh[il][jl];
            acc0 += wv * h_sh[il][lane];
            acc1 += wv * h_sh[il][lane + 32];
        }
        __syncthreads();
    }
    u_sh[jl][lane]      = acc0;
    u_sh[jl][lane + 32] = acc1;
    __syncthreads();
    for (int idx = t; idx < 1024; idx += 512) {
        const int bb = idx >> 4, jj = idx & 15;
        g_u[bb * HH + j0 + jj] = u_sh[jj][bb];
    }
}

// ---------------------------------------------------------------------------
// K2: PERSISTENT streaming pass, fixed-offset softmax.
// grid = 296 resident CTAs (2/SM), block = 256 (8 warps). Each CTA strides
// over 4096 (b, 64-row-chunk) items -> no wave quantization (1.2% tail).
// Inner loop = measured-best R6 body: 2 rows/warp/iter, __ldcs, MLP=8.
// ---------------------------------------------------------------------------
__global__ void __launch_bounds__(256) k2_flash(const float* __restrict__ hs,
                                                const int* __restrict__ mask) {
    const int warp  = threadIdx.x >> 5;
    const int lane  = threadIdx.x & 31;
    const float4* hs4 = reinterpret_cast<const float4*>(hs);

    __shared__ float sl[8];
    __shared__ float sacc[8][HH];   // 16 KB

    for (int item = blockIdx.x; item < NITEM; item += GRID2) {
        const int b     = item >> 6;
        const int chunk = item & 63;

        float4 u4[4];
        const float4* up = reinterpret_cast<const float4*>(g_u + b * HH);
#pragma unroll
        for (int k = 0; k < 4; k++) u4[k] = up[lane + 32 * k];

        float l = 0.f;
        float4 acc[4];
#pragma unroll
        for (int k = 0; k < 4; k++) acc[k] = make_float4(0.f, 0.f, 0.f, 0.f);

        const int base = chunk * 64 + warp * 8;

#pragma unroll
        for (int it = 0; it < 4; it++) {
            const int s0 = base + it * 2;
            const int s1 = s0 + 1;
            const size_t r0 = ((size_t)s0 * BB + b) * (HH / 4);
            const size_t r1 = ((size_t)s1 * BB + b) * (HH / 4);
            float4 x0[4], x1[4];
#pragma unroll
            for (int k = 0; k < 4; k++) x0[k] = __ldcs(&hs4[r0 + lane + 32 * k]);
#pragma unroll
            for (int k = 0; k < 4; k++) x1[k] = __ldcs(&hs4[r1 + lane + 32 * k]);
            const int mk0 = mask[b * SS + s0];
            const int mk1 = mask[b * SS + s1];

            float d0 = 0.f, d1 = 0.f;
#pragma unroll
            for (int k = 0; k < 4; k++) {
                d0 += x0[k].x * u4[k].x + x0[k].y * u4[k].y +
                      x0[k].z * u4[k].z + x0[k].w * u4[k].w;
                d1 += x1[k].x * u4[k].x + x1[k].y * u4[k].y +
                      x1[k].z * u4[k].z + x1[k].w * u4[k].w;
            }
#pragma unroll
            for (int off = 16; off; off >>= 1) {
                d0 += __shfl_xor_sync(0xffffffffu, d0, off);
                d1 += __shfl_xor_sync(0xffffffffu, d1, off);
            }
            float p0 = __expf(d0 - CEXP);
            float p1 = __expf(d1 - CEXP);
            p0 = mk0 ? p0 : 0.f;
            p1 = mk1 ? p1 : 0.f;
            l += p0 + p1;
#pragma unroll
            for (int k = 0; k < 4; k++) {
                acc[k].x += p0 * x0[k].x + p1 * x1[k].x;
                acc[k].y += p0 * x0[k].y + p1 * x1[k].y;
                acc[k].z += p0 * x0[k].z + p1 * x1[k].z;
                acc[k].w += p0 * x0[k].w + p1 * x1[k].w;
            }
        }

        // ---- block combine: plain sums across 8 warps ----
        __syncthreads();   // prior item's smem reads complete before overwrite
        if (lane == 0) sl[warp] = l;
        float4* srow = reinterpret_cast<float4*>(sacc[warp]);
#pragma unroll
        for (int k = 0; k < 4; k++) srow[lane + 32 * k] = acc[k];
        __syncthreads();

        if (threadIdx.x == 0) {
            float L = 0.f;
#pragma unroll
            for (int w = 0; w < 8; w++) L += sl[w];
            g_pl[item] = L;
        }
        for (int h = threadIdx.x; h < HH; h += 256) {
            float A = 0.f;
#pragma unroll
            for (int w = 0; w < 8; w++) A += sacc[w][h];
            g_pacc[(size_t)item * HH + h] = A;
        }
    }
}

// ---------------------------------------------------------------------------
// K3a: combine NCH chunk-partials -> c_t  (plain sums; shift cancels in A/L)
// ---------------------------------------------------------------------------
__global__ void __launch_bounds__(512) k3a_combine() {
    const int b = blockIdx.x, h = threadIdx.x;
    __shared__ float slb[NCH];
    if (h < NCH) slb[h] = g_pl[b * NCH + h];
    __syncthreads();
    float L = 0.f;
#pragma unroll
    for (int c = 0; c < NCH; c++) L += slb[c];
    float A = 0.f;
#pragma unroll 8
    for (int c = 0; c < NCH; c++)
        A += g_pacc[(size_t)(b * NCH + c) * HH + h];
    g_ct[b * HH + h] = A / L;
}

// ---------------------------------------------------------------------------
// K3b: split-K GEMM partials: opart[ks][o][b] = sum_{k in slice} W_r[o,k]*cat[b,k]
// grid = (16 o-tiles, 32 k-slices) = 512 CTAs, block = 256.
// ---------------------------------------------------------------------------
__global__ void __launch_bounds__(256) k3b_gemm(const float* __restrict__ h_t,
                                                const float* __restrict__ W_r) {
    __shared__ float cat_sh[64][68];
    __shared__ float W_sh[32][68];
    const int t = threadIdx.x;
    const int otile = blockIdx.x;
    const int ks    = blockIdx.y;
    const int kbase = ks * KSL;

    const float* src = (kbase < HH) ? (g_ct + kbase) : (h_t + (kbase - HH));
    for (int i = t; i < 64 * 8; i += 256) {
        const int bb = i >> 3, k4 = i & 7;
        const float4 v = *reinterpret_cast<const float4*>(src + bb * HH + k4 * 4);
        *reinterpret_cast<float4*>(&cat_sh[bb][k4 * 4]) = v;
    }
    for (int i = t; i < 32 * 8; i += 256) {
        const int oo = i >> 3, k4 = i & 7;
        const float4 v = *reinterpret_cast<const float4*>(
            W_r + (size_t)(otile * 32 + oo) * (2 * HH) + kbase + k4 * 4);
        *reinterpret_cast<float4*>(&W_sh[oo][k4 * 4]) = v;
    }
    __syncthreads();

    const int b = t & 63, og = t >> 6;
    float acc[8];
#pragma unroll
    for (int j = 0; j < 8; j++) acc[j] = 0.f;

#pragma unroll
    for (int kk = 0; kk < 8; kk++) {
        const float4 c4 = *reinterpret_cast<const float4*>(&cat_sh[b][kk * 4]);
#pragma unroll
        for (int j = 0; j < 8; j++) {
            const float4 w4 =
                *reinterpret_cast<const float4*>(&W_sh[og * 8 + j][kk * 4]);
            acc[j] += c4.x * w4.x + c4.y * w4.y + c4.z * w4.z + c4.w * w4.w;
        }
    }
#pragma unroll
    for (int j = 0; j < 8; j++) {
        const int o = otile * 32 + og * 8 + j;
        g_opart[(size_t)ks * HH * BB + o * BB + b] = acc[j];
    }
}

// ---------------------------------------------------------------------------
// K3c: out[b,o] = tanh(b_r[o] + sum_ks opart[ks][o][b]); smem transpose write.
// ---------------------------------------------------------------------------
__global__ void __launch_bounds__(512) k3c_fin(const float* __restrict__ b_r,
                                               float* __restrict__ out) {
    __shared__ float sh[8][65];
    const int c = blockIdx.x;
    const int t = threadIdx.x;
    const int j = t >> 6, b = t & 63;
    const int o = c * 8 + j;
    float s = 0.f;
#pragma unroll
    for (int ks = 0; ks < KS; ks++)
        s += g_opart[(size_t)ks * HH * BB + o * BB + b];
    sh[j][b] = tanhf(s + b_r[o]);
    __syncthreads();
    const int b2 = t >> 3, j2 = t & 7;
    out[b2 * HH + c * 8 + j2] = sh[j2][b2];
}

// ---------------------------------------------------------------------------
extern "C" void kernel_launch(void* const* d_in, const int* in_sizes, int n_in,
                              void* d_out, int out_size) {
    const float* hs   = (const float*)d_in[0];   // [S,B,H]
    const float* h_t  = (const float*)d_in[1];   // [B,H]
    const int*   mask = (const int*)  d_in[2];   // [B,S]
    const float* W_a  = (const float*)d_in[3];   // [H,H]
    // d_in[4] = b_a : cancels in softmax (per-b constant)
    const float* W_r  = (const float*)d_in[5];   // [H,2H]
    const float* b_r  = (const float*)d_in[6];   // [H]
    float* out = (float*)d_out;                  // [B,H]

    k1_proj<<<HH / 16, 512>>>(W_a, h_t);
    k2_flash<<<GRID2, 256>>>(hs, mask);
    k3a_combine<<<BB, 512>>>();
    k3b_gemm<<<dim3(16, KS), 256>>>(h_t, W_r);
    k3c_fin<<<BB, 512>>>(b_r, out);
}

// round 9
// speedup vs baseline: 1.1618x; 1.1618x over previous
#include <cuda_runtime.h>
#include <math.h>

#define SS 4096
#define BB 64
#define HH 512
#define SPL 16
#define CH (SS / SPL)   // 256 rows per (b, split)
#define KS 32           // split-K slices for final GEMM
#define KSL 32          // K per slice (2H / KS)
#define CEXP 32.0f      // fixed softmax shift (cancels exactly in acc/l)

// Scratch (device globals — no allocation allowed)
__device__ float g_u[BB * HH];               // u[b,j] = sum_i W_a[i,j] h_t[b,i]
__device__ float g_ct[BB * HH];              // c_t
__device__ float g_pl[BB * SPL];             // partial sum-exp
__device__ float g_pacc[BB * SPL * HH];      // partial weighted accumulators
__device__ float g_opart[KS * HH * BB];      // [ks][o][b] GEMM partials (4 MB)

// ---------------------------------------------------------------------------
// K1: u[b,j] = sum_i W_a[i,j] * h_t[b,i].  W_a read EXACTLY ONCE total.
// grid = 64 CTAs (8 j-cols each), block = 256 (warp = j-col, lanes = b, 2 b/thr)
// ---------------------------------------------------------------------------
__global__ void __launch_bounds__(256) k1_proj(const float* __restrict__ W_a,
                                               const float* __restrict__ h_t) {
    __shared__ float h_sh[64][65];
    __shared__ float W_sh[64][8];
    __shared__ float u_sh[8][65];
    const int t = threadIdx.x;
    const int jl = t >> 5, lane = t & 31;
    const int j0 = blockIdx.x * 8;

    float acc0 = 0.f, acc1 = 0.f;
    for (int c = 0; c < 8; c++) {
        const int ibase = c * 64;
        for (int idx = t; idx < 64 * 64; idx += 256) {
            const int bb = idx >> 6, il = idx & 63;
            h_sh[il][bb] = h_t[bb * HH + ibase + il];
        }
        for (int idx = t; idx < 64 * 8; idx += 256) {
            const int il = idx >> 3, jj = idx & 7;
            W_sh[il][jj] = W_a[(ibase + il) * HH + j0 + jj];
        }
        __syncthreads();
#pragma unroll 16
        for (int il = 0; il < 64; il++) {
            const float wv = W_sh[il][jl];
            acc0 += wv * h_sh[il][lane];
            acc1 += wv * h_sh[il][lane + 32];
        }
        __syncthreads();
    }
    u_sh[jl][lane]      = acc0;
    u_sh[jl][lane + 32] = acc1;
    __syncthreads();
    for (int idx = t; idx < 512; idx += 256) {
        const int bb = idx >> 3, jj = idx & 7;
        g_u[bb * HH + j0 + jj] = u_sh[jj][bb];
    }
}

// ---------------------------------------------------------------------------
// K2: single streaming pass, fixed-offset softmax, 4 rows/warp/iter (MLP=16).
// grid = (SPL, B) = 1024 CTAs, block = 256 (8 warps), 32 rows/warp.
// ---------------------------------------------------------------------------
__global__ void __launch_bounds__(256) k2_flash(const float* __restrict__ hs,
                                                const int* __restrict__ mask) {
    const int split = blockIdx.x;
    const int b     = blockIdx.y;
    const int warp  = threadIdx.x >> 5;
    const int lane  = threadIdx.x & 31;

    float4 u4[4];
    const float4* up = reinterpret_cast<const float4*>(g_u + b * HH);
#pragma unroll
    for (int k = 0; k < 4; k++) u4[k] = up[lane + 32 * k];

    float l = 0.f;
    float4 acc[4];
#pragma unroll
    for (int k = 0; k < 4; k++) acc[k] = make_float4(0.f, 0.f, 0.f, 0.f);

    const int base = split * CH + warp * 32;
    const float4* hs4 = reinterpret_cast<const float4*>(hs);

    for (int it = 0; it < 8; it++) {
        const int s = base + it * 4;
        float4 x[4][4];
        int mk[4];
#pragma unroll
        for (int r = 0; r < 4; r++) {
            const size_t rr = ((size_t)(s + r) * BB + b) * (HH / 4);
#pragma unroll
            for (int k = 0; k < 4; k++)
                x[r][k] = __ldcs(&hs4[rr + lane + 32 * k]);
            mk[r] = mask[b * SS + s + r];
        }

        float d[4];
#pragma unroll
        for (int r = 0; r < 4; r++) {
            float dd = 0.f;
#pragma unroll
            for (int k = 0; k < 4; k++)
                dd += x[r][k].x * u4[k].x + x[r][k].y * u4[k].y +
                      x[r][k].z * u4[k].z + x[r][k].w * u4[k].w;
            d[r] = dd;
        }
#pragma unroll
        for (int off = 16; off; off >>= 1) {
#pragma unroll
            for (int r = 0; r < 4; r++)
                d[r] += __shfl_xor_sync(0xffffffffu, d[r], off);
        }
        float p[4];
#pragma unroll
        for (int r = 0; r < 4; r++) {
            float pp = __expf(d[r] - CEXP);
            p[r] = mk[r] ? pp : 0.f;
        }
        l += (p[0] + p[1]) + (p[2] + p[3]);
#pragma unroll
        for (int k = 0; k < 4; k++) {
            acc[k].x += p[0] * x[0][k].x + p[1] * x[1][k].x +
                        p[2] * x[2][k].x + p[3] * x[3][k].x;
            acc[k].y += p[0] * x[0][k].y + p[1] * x[1][k].y +
                        p[2] * x[2][k].y + p[3] * x[3][k].y;
            acc[k].z += p[0] * x[0][k].z + p[1] * x[1][k].z +
                        p[2] * x[2][k].z + p[3] * x[3][k].z;
            acc[k].w += p[0] * x[0][k].w + p[1] * x[1][k].w +
                        p[2] * x[2][k].w + p[3] * x[3][k].w;
        }
    }

    // ---- block combine: plain sums across 8 warps ----
    __shared__ float sl[8];
    __shared__ float sacc[8][HH];   // 16 KB
    if (lane == 0) sl[warp] = l;
    float4* srow = reinterpret_cast<float4*>(sacc[warp]);
#pragma unroll
    for (int k = 0; k < 4; k++) srow[lane + 32 * k] = acc[k];
    __syncthreads();

    const int pidx = b * SPL + split;
    if (threadIdx.x == 0) {
        float L = 0.f;
#pragma unroll
        for (int w = 0; w < 8; w++) L += sl[w];
        g_pl[pidx] = L;
    }
    for (int h = threadIdx.x; h < HH; h += 256) {
        float A = 0.f;
#pragma unroll
        for (int w = 0; w < 8; w++) A += sacc[w][h];
        g_pacc[(size_t)pidx * HH + h] = A;
    }
}

// ---------------------------------------------------------------------------
// K3a: combine SPL partials -> c_t  (plain sums; shift cancels in A/L)
// ---------------------------------------------------------------------------
__global__ void __launch_bounds__(512) k3a_combine() {
    const int b = blockIdx.x, h = threadIdx.x;
    float L = 0.f, A = 0.f;
#pragma unroll
    for (int s = 0; s < SPL; s++) {
        L += g_pl[b * SPL + s];
        A += g_pacc[(size_t)(b * SPL + s) * HH + h];
    }
    g_ct[b * HH + h] = A / L;
}

// ---------------------------------------------------------------------------
// K3b: split-K GEMM partials: opart[ks][o][b] = sum_{k in slice} W_r[o,k]*cat[b,k]
// grid = (32 o-tiles of 16, 32 k-slices) = 1024 CTAs, block = 256.
// W_r still read exactly once total.
// ---------------------------------------------------------------------------
__global__ void __launch_bounds__(256) k3b_gemm(const float* __restrict__ h_t,
                                                const float* __restrict__ W_r) {
    __shared__ float cat_sh[64][36];   // [b][k], 32 k + pad
    __shared__ float W_sh[16][36];     // [o_local][k]
    const int t = threadIdx.x;
    const int otile = blockIdx.x;
    const int ks    = blockIdx.y;
    const int kbase = ks * KSL;

    const float* src = (kbase < HH) ? (g_ct + kbase) : (h_t + (kbase - HH));
    for (int i = t; i < 64 * 8; i += 256) {           // 512 float4
        const int bb = i >> 3, k4 = i & 7;
        const float4 v = *reinterpret_cast<const float4*>(src + bb * HH + k4 * 4);
        *reinterpret_cast<float4*>(&cat_sh[bb][k4 * 4]) = v;
    }
    if (t < 16 * 8) {                                  // 128 float4
        const int oo = t >> 3, k4 = t & 7;
        const float4 v = *reinterpret_cast<const float4*>(
            W_r + (size_t)(otile * 16 + oo) * (2 * HH) + kbase + k4 * 4);
        *reinterpret_cast<float4*>(&W_sh[oo][k4 * 4]) = v;
    }
    __syncthreads();

    const int b = t & 63, og = t >> 6;                // og: 0..3, 4 o each
    float acc[4];
#pragma unroll
    for (int j = 0; j < 4; j++) acc[j] = 0.f;

#pragma unroll
    for (int kk = 0; kk < 8; kk++) {
        const float4 c4 = *reinterpret_cast<const float4*>(&cat_sh[b][kk * 4]);
#pragma unroll
        for (int j = 0; j < 4; j++) {
            const float4 w4 =
                *reinterpret_cast<const float4*>(&W_sh[og * 4 + j][kk * 4]);
            acc[j] += c4.x * w4.x + c4.y * w4.y + c4.z * w4.z + c4.w * w4.w;
        }
    }
#pragma unroll
    for (int j = 0; j < 4; j++) {
        const int o = otile * 16 + og * 4 + j;
        g_opart[(size_t)ks * HH * BB + o * BB + b] = acc[j];   // coalesced in b
    }
}

// ---------------------------------------------------------------------------
// K3c: out[b,o] = tanh(b_r[o] + sum_ks opart[ks][o][b]); smem transpose write.
// ---------------------------------------------------------------------------
__global__ void __launch_bounds__(512) k3c_fin(const float* __restrict__ b_r,
                                               float* __restrict__ out) {
    __shared__ float sh[8][65];
    const int c = blockIdx.x;
    const int t = threadIdx.x;
    const int j = t >> 6, b = t & 63;
    const int o = c * 8 + j;
    float s = 0.f;
#pragma unroll
    for (int ks = 0; ks < KS; ks++)
        s += g_opart[(size_t)ks * HH * BB + o * BB + b];
    sh[j][b] = tanhf(s + b_r[o]);
    __syncthreads();
    const int b2 = t >> 3, j2 = t & 7;
    out[b2 * HH + c * 8 + j2] = sh[j2][b2];
}

// ---------------------------------------------------------------------------
extern "C" void kernel_launch(void* const* d_in, const int* in_sizes, int n_in,
                              void* d_out, int out_size) {
    const float* hs   = (const float*)d_in[0];   // [S,B,H]
    const float* h_t  = (const float*)d_in[1];   // [B,H]
    const int*   mask = (const int*)  d_in[2];   // [B,S]
    const float* W_a  = (const float*)d_in[3];   // [H,H]
    // d_in[4] = b_a : cancels in softmax (per-b constant)
    const float* W_r  = (const float*)d_in[5];   // [H,2H]
    const float* b_r  = (const float*)d_in[6];   // [H]
    float* out = (float*)d_out;                  // [B,H]

    k1_proj<<<HH / 8, 256>>>(W_a, h_t);
    k2_flash<<<dim3(SPL, BB), 256>>>(hs, mask);
    k3a_combine<<<BB, 512>>>();
    k3b_gemm<<<dim3(32, KS), 256>>>(h_t, W_r);
    k3c_fin<<<BB, 512>>>(b_r, out);
}